// round 8
// baseline (speedup 1.0000x reference)
#include <cuda_runtime.h>
#include <cuda_bf16.h>
#include <math_constants.h>

#define NU 200000
#define NA 100000
#define NC 500
#define DD 64
#define HH 4
#define LL 2
#define ETOT 4200000

typedef unsigned long long ull;

#define FMA_F32X2(acc, a, b) \
    asm("fma.rn.f32x2 %0, %1, %2, %0;" : "+l"(acc) : "l"(a), "l"(b))

// ---------------- scratch (device globals; no allocation) -------------------
__device__ float  g_hsU[4][NU * DD];
__device__ float  g_hsA[2][NA * DD];
__device__ float  g_hsC[2][NC * DD];
__device__ float4 g_as [8][NU];
__device__ float4 g_ad [8][NU];
__device__ float  g_xu [NU * DD];
__device__ float  g_xa [NA * DD];
__device__ float  g_xc [NC * DD];
__device__ float  g_vdst[LL * 8 * DD * HH];
__device__ int    g_off [8 * (NU + 1)];
__device__ int    g_cur [8 * (NU + 1)];
__device__ int    g_srcs[ETOT];
__device__ int    g_bsum[2048];

__device__ __forceinline__ float lrelu(float x, float s) { return x > 0.f ? x : s * x; }
__device__ __forceinline__ float pick(float4 v, int h) {
    return h == 0 ? v.x : h == 1 ? v.y : h == 2 ? v.z : v.w;
}

struct EPtrs  { const int* p[8]; };
struct CsrCfg { int E[8]; int n[8]; int nb[8]; int bstart[9]; int eb[8]; };
struct Ptr4   { float4 *p0, *p1, *p2, *p3; };

// ---------------- batched CSR build -----------------------------------------
__global__ void hist_all_k(EPtrs ep, CsrCfg cfg, int* __restrict__ cnt) {
    int t = blockIdx.y;
    int e = blockIdx.x * 256 + threadIdx.x;
    if (e < cfg.E[t]) atomicAdd(&cnt[t * (NU + 1) + ep.p[t][cfg.E[t] + e]], 1);
}

__global__ void scan1_all_k(const int* __restrict__ cnt, CsrCfg cfg,
                            int* __restrict__ off, int* __restrict__ bsum) {
    __shared__ int sh[1024];
    int bid = blockIdx.x;
    int t = 0;
#pragma unroll
    for (int k = 0; k < 8; k++) if (bid >= cfg.bstart[k + 1]) t = k + 1;
    int lb = bid - cfg.bstart[t];
    int tid = threadIdx.x;
    int it = lb * 1024 + tid;
    int n = cfg.n[t];
    int v = (it < n) ? cnt[t * (NU + 1) + it] : 0;
    sh[tid] = v; __syncthreads();
#pragma unroll
    for (int d = 1; d < 1024; d <<= 1) {
        int tv = (tid >= d) ? sh[tid - d] : 0;
        __syncthreads();
        sh[tid] += tv;
        __syncthreads();
    }
    if (it < n) off[t * (NU + 1) + it] = sh[tid] - v;
    if (tid == 1023) bsum[t * 256 + lb] = sh[1023];
}

__global__ void scan2_all_k(int* __restrict__ bsum, CsrCfg cfg) {
    __shared__ int sh[256];
    int t = blockIdx.x, tid = threadIdx.x;
    int nb = cfg.nb[t];
    int v = (tid < nb) ? bsum[t * 256 + tid] : 0;
    sh[tid] = v; __syncthreads();
#pragma unroll
    for (int d = 1; d < 256; d <<= 1) {
        int tv = (tid >= d) ? sh[tid - d] : 0;
        __syncthreads();
        sh[tid] += tv;
        __syncthreads();
    }
    if (tid < nb) bsum[t * 256 + tid] = sh[tid] - v;
}

__global__ void scan3_all_k(int* __restrict__ off, CsrCfg cfg,
                            const int* __restrict__ bsum) {
    int bid = blockIdx.x;
    int t = 0;
#pragma unroll
    for (int k = 0; k < 8; k++) if (bid >= cfg.bstart[k + 1]) t = k + 1;
    int lb = bid - cfg.bstart[t];
    int it = lb * 1024 + threadIdx.x;
    if (it < cfg.n[t]) off[t * (NU + 1) + it] += bsum[t * 256 + lb];
}

__global__ void scatter_all_k(EPtrs ep, CsrCfg cfg, int* __restrict__ cur,
                              int* __restrict__ srcs) {
    int t = blockIdx.y;
    int e = blockIdx.x * 256 + threadIdx.x;
    if (e >= cfg.E[t]) return;
    int c = ep.p[t][cfg.E[t] + e];
    int pos = atomicAdd(&cur[t * (NU + 1) + c], 1);
    srcs[cfg.eb[t] + pos] = ep.p[t][e];
}

// ---------------- dense precompute ------------------------------------------
__global__ void compute_v_k(const float* __restrict__ W, const float* __restrict__ att,
                            float* __restrict__ v) {
    int idx = blockIdx.x * blockDim.x + threadIdx.x;
    if (idx >= LL * 8 * DD * HH) return;
    int lt = idx >> 8, k = (idx >> 2) & 63, h = idx & 3;
    const float* Wr = W + (lt * 64 + k) * 64 + h * 16;
    const float* ar = att + lt * 64 + h * 16;
    float s = 0.f;
#pragma unroll
    for (int c = 0; c < 16; c++) s += Wr[c] * ar[c];
    v[idx] = s;
}

// hs = x @ W (64x64), f32x2 FMA; fused a_src + (optionally) ad for nt dst types.
__global__ __launch_bounds__(256, 3) void gemm5_k(
        const float* __restrict__ x, const float* __restrict__ W,
        const float* __restrict__ att, float* __restrict__ hs,
        float4* __restrict__ as_, int N,
        const float* __restrict__ vdst, int4 adt, int nt, Ptr4 adp) {
    __shared__ __align__(16) float  Xs[64][68];
    __shared__ __align__(16) float4 Wq[16][72];
    __shared__ __align__(16) float  vsm[64][4][4];   // [k][h][ti]
    int tid  = threadIdx.x;
    int base = blockIdx.x * 64;
    int nrows = N - base; if (nrows > 64) nrows = 64;

    for (int idx = tid; idx < 1024; idx += 256) {
        int kq = idx >> 6, j = idx & 63;
        int p = j + (j >> 3);
        Wq[kq][p] = make_float4(W[(4 * kq + 0) * 64 + j], W[(4 * kq + 1) * 64 + j],
                                W[(4 * kq + 2) * 64 + j], W[(4 * kq + 3) * 64 + j]);
    }
    for (int idx = tid; idx < 1024; idx += 256) {
        int row = idx >> 4, kq = idx & 15;
        float4 v = (row < nrows) ? *(const float4*)&x[(size_t)(base + row) * 64 + kq * 4]
                                 : make_float4(0.f, 0.f, 0.f, 0.f);
        *(float4*)&Xs[row][kq * 4] = v;
    }
    if (nt > 0) {
        for (int idx = tid; idx < 1024; idx += 256) {
            int k = idx >> 4, h = (idx >> 2) & 3, ti = idx & 3;
            int lt = ti == 0 ? adt.x : ti == 1 ? adt.y : ti == 2 ? adt.z : adt.w;
            vsm[k][h][ti] = (ti < nt) ? vdst[(size_t)lt * 256 + k * 4 + h] : 0.f;
        }
    }
    __syncthreads();

    int tx = tid & 15, ty = tid >> 4;
    int pcol[4];
#pragma unroll
    for (int c = 0; c < 4; c++) {
        int col = tx + 16 * c;
        pcol[c] = col + (col >> 3);
    }

    ull acc[4][4];
#pragma unroll
    for (int r = 0; r < 4; r++)
#pragma unroll
        for (int c = 0; c < 4; c++) acc[r][c] = 0ull;

#pragma unroll
    for (int kq = 0; kq < 16; kq++) {
        ulonglong2 a[4], b[4];
#pragma unroll
        for (int r = 0; r < 4; r++)
            a[r] = *(const ulonglong2*)&Xs[ty * 4 + r][kq * 4];
#pragma unroll
        for (int c = 0; c < 4; c++)
            b[c] = *(const ulonglong2*)&Wq[kq][pcol[c]];
#pragma unroll
        for (int r = 0; r < 4; r++)
#pragma unroll
            for (int c = 0; c < 4; c++) {
                FMA_F32X2(acc[r][c], a[r].x, b[c].x);
                FMA_F32X2(acc[r][c], a[r].y, b[c].y);
            }
    }

    float s[4][4];
#pragma unroll
    for (int r = 0; r < 4; r++)
#pragma unroll
        for (int c = 0; c < 4; c++) {
            float2 v = *(float2*)&acc[r][c];
            s[r][c] = v.x + v.y;
        }

#pragma unroll
    for (int r = 0; r < 4; r++) {
        int row = ty * 4 + r;
        if (row < nrows) {
            float* hp = &hs[(size_t)(base + row) * 64 + tx];
#pragma unroll
            for (int c = 0; c < 4; c++) hp[16 * c] = s[r][c];
        }
    }

    float attv[4];
#pragma unroll
    for (int c = 0; c < 4; c++) attv[c] = att[tx + 16 * c];
    float p[4][4];
#pragma unroll
    for (int r = 0; r < 4; r++)
#pragma unroll
        for (int c = 0; c < 4; c++) p[r][c] = s[r][c] * attv[c];
#pragma unroll
    for (int mask = 1; mask < 16; mask <<= 1)
#pragma unroll
        for (int r = 0; r < 4; r++)
#pragma unroll
            for (int c = 0; c < 4; c++)
                p[r][c] += __shfl_xor_sync(0xffffffffu, p[r][c], mask);
    if (tx == 0) {
#pragma unroll
        for (int r = 0; r < 4; r++) {
            int row = ty * 4 + r;
            if (row < nrows)
                as_[base + row] = make_float4(p[r][0], p[r][1], p[r][2], p[r][3]);
        }
    }

    // fused dst scores: thread (n, h) computes ad for up to 4 types
    if (nt > 0) {
        int n = tid >> 2, h = tid & 3;
        if (n < nrows) {
            float s0 = 0.f, s1 = 0.f, s2 = 0.f, s3 = 0.f;
#pragma unroll
            for (int kq = 0; kq < 16; kq++) {
                float4 xv = *(const float4*)&Xs[n][kq * 4];
                float xa[4] = {xv.x, xv.y, xv.z, xv.w};
#pragma unroll
                for (int kk = 0; kk < 4; kk++) {
                    float4 vv = *(const float4*)&vsm[kq * 4 + kk][h][0];
                    s0 += xa[kk] * vv.x;
                    s1 += xa[kk] * vv.y;
                    s2 += xa[kk] * vv.z;
                    s3 += xa[kk] * vv.w;
                }
            }
            size_t o = (size_t)(base + n) * 4 + h;
            ((float*)adp.p0)[o] = s0;
            if (nt > 1) ((float*)adp.p1)[o] = s1;
            if (nt > 2) ((float*)adp.p2)[o] = s2;
            if (nt > 3) ((float*)adp.p3)[o] = s3;
        }
    }
}

// ---------------- fused multi-type aggregation + epilogue --------------------
struct AggT {
    const int*    off;
    const int*    srcs;
    const float*  hs;
    const float4* as;
    const float4* ad;
};

// Order-independent softmax (no max shift — logits are O(0.1)); unroll x4 for MLP.
__device__ __forceinline__ float proc_type(const AggT& T, int g, int j, int h) {
    int s0 = T.off[g], s1 = T.off[g + 1];
    if (s0 == s1) return 0.f;
    float b = pick(T.ad[g], h);
    float d = 0.f, acc = 0.f;
    int s = s0;
    for (; s + 4 <= s1; s += 4) {
        int r0 = T.srcs[s], r1 = T.srcs[s + 1], r2 = T.srcs[s + 2], r3 = T.srcs[s + 3];
        float4 A0 = T.as[r0], A1 = T.as[r1], A2 = T.as[r2], A3 = T.as[r3];
        float h0 = T.hs[(size_t)r0 * 64 + j], h1 = T.hs[(size_t)r1 * 64 + j];
        float h2 = T.hs[(size_t)r2 * 64 + j], h3 = T.hs[(size_t)r3 * 64 + j];
        float p0 = __expf(lrelu(pick(A0, h) + b, 0.2f));
        float p1 = __expf(lrelu(pick(A1, h) + b, 0.2f));
        float p2 = __expf(lrelu(pick(A2, h) + b, 0.2f));
        float p3 = __expf(lrelu(pick(A3, h) + b, 0.2f));
        d   += (p0 + p1) + (p2 + p3);
        acc += h0 * p0 + h1 * p1 + h2 * p2 + h3 * p3;
    }
    for (; s < s1; s++) {
        int r = T.srcs[s];
        float4 A = T.as[r];
        float hv = T.hs[(size_t)r * 64 + j];
        float pw = __expf(lrelu(pick(A, h) + b, 0.2f));
        d += pw;
        acc += hv * pw;
    }
    return acc / d;
}

__global__ void agg_multi_k(AggT a0, AggT a1, AggT a2, AggT a3, int nt,
                            const float* __restrict__ bias, int4 tids, int l,
                            float* __restrict__ xout, float* __restrict__ accv,
                            const float* __restrict__ xin, int Nd) {
    int g = blockIdx.x * 4 + (threadIdx.x >> 6);
    if (g >= Nd) return;
    int j = threadIdx.x & 63, h = j >> 4;

    float total = proc_type(a0, g, j, h);
    if (nt > 1) total += proc_type(a1, g, j, h);
    if (nt > 2) total += proc_type(a2, g, j, h);
    if (nt > 3) total += proc_type(a3, g, j, h);

    float bs = bias[(size_t)(l * 8 + tids.x) * 64 + j];
    if (nt > 1) bs += bias[(size_t)(l * 8 + tids.y) * 64 + j];
    if (nt > 2) bs += bias[(size_t)(l * 8 + tids.z) * 64 + j];
    if (nt > 3) bs += bias[(size_t)(l * 8 + tids.w) * 64 + j];

    float v = total + bs;
    v = v > 0.f ? v : 0.01f * v;
    size_t o = (size_t)g * 64 + j;
    if (xout) xout[o] = v;
    if (accv) accv[o] = xin ? (xin[o] + v) : ((accv[o] + v) * (1.f / 3.f));
}

// category dst: block per node, 4 chunks, 2 types, fused epilogue (layer 0 only)
__device__ float proc_cat_type(const AggT& T, int g, int tid, int chunk, int j, int h,
                               float sd[4][4], float sacc[4][64]) {
    int s0 = T.off[g], s1 = T.off[g + 1];
    float b = pick(T.ad[g], h);
    float d = 0.f, acc = 0.f;
    for (int s = s0 + chunk; s < s1; s += 4) {
        int r = T.srcs[s];
        float4 a4 = T.as[r];
        float hv = T.hs[(size_t)r * 64 + j];
        float pw = __expf(lrelu(pick(a4, h) + b, 0.2f));
        d += pw;
        acc += hv * pw;
    }
    if ((j & 15) == 0) sd[chunk][h] = d;
    sacc[chunk][j] = acc;
    __syncthreads();
    float out = 0.f;
    if (tid < 64) {
        int hh = tid >> 4;
        float dg = sd[0][hh] + sd[1][hh] + sd[2][hh] + sd[3][hh];
        out = (sacc[0][tid] + sacc[1][tid] + sacc[2][tid] + sacc[3][tid]) / (dg + 1e-16f);
    }
    __syncthreads();
    return out;
}

__global__ void agg_cat_k(AggT a0, AggT a1, const float* __restrict__ bias,
                          int t0, int t1, int l, float* __restrict__ xout) {
    int g = blockIdx.x;
    int tid = threadIdx.x, chunk = tid >> 6, j = tid & 63, h = j >> 4;
    __shared__ float sd[4][4], sacc[4][64];
    float tot = proc_cat_type(a0, g, tid, chunk, j, h, sd, sacc);
    tot      += proc_cat_type(a1, g, tid, chunk, j, h, sd, sacc);
    if (tid < 64) {
        float v = tot + bias[(size_t)(l * 8 + t0) * 64 + tid]
                      + bias[(size_t)(l * 8 + t1) * 64 + tid];
        v = v > 0.f ? v : 0.01f * v;
        xout[(size_t)g * 64 + tid] = v;
    }
}

// ---------------- host orchestration ----------------------------------------
extern "C" void kernel_launch(void* const* d_in, const int* in_sizes, int n_in,
                              void* d_out, int out_size) {
    const float* x_user    = (const float*)d_in[0];
    const float* x_article = (const float*)d_in[1];
    const float* x_cat     = (const float*)d_in[2];
    const float* Wsrc      = (const float*)d_in[3];
    const float* Wdst      = (const float*)d_in[4];
    const float* att_src   = (const float*)d_in[5];
    const float* att_dst   = (const float*)d_in[6];
    const float* bias      = (const float*)d_in[7];

    int Nu = in_sizes[0] / DD, Na = in_sizes[1] / DD, Nc = in_sizes[2] / DD;

    float *xu, *xa, *xc, *vdst;
    float4 *as4, *ad4;
    int *offb, *curb, *srcsb, *bsum;
    float *hsU, *hsA, *hsC;
    cudaGetSymbolAddress((void**)&hsU,  g_hsU);
    cudaGetSymbolAddress((void**)&hsA,  g_hsA);
    cudaGetSymbolAddress((void**)&hsC,  g_hsC);
    cudaGetSymbolAddress((void**)&as4,  g_as);
    cudaGetSymbolAddress((void**)&ad4,  g_ad);
    cudaGetSymbolAddress((void**)&xu,   g_xu);
    cudaGetSymbolAddress((void**)&xa,   g_xa);
    cudaGetSymbolAddress((void**)&xc,   g_xc);
    cudaGetSymbolAddress((void**)&vdst, g_vdst);
    cudaGetSymbolAddress((void**)&offb, g_off);
    cudaGetSymbolAddress((void**)&curb, g_cur);
    cudaGetSymbolAddress((void**)&srcsb, g_srcs);
    cudaGetSymbolAddress((void**)&bsum, g_bsum);

    cudaStream_t s = 0;
    float* acc_u = (float*)d_out;
    float* acc_a = (float*)d_out + (size_t)Nu * DD;

    int sizes[3] = {Nu, Na, Nc};
    const int stp[8] = {0, 1, 0, 0, 1, 2, 0, 2};
    const int dtp[8] = {1, 0, 0, 0, 2, 1, 2, 0};
    float* hsp[8];
    hsp[0] = hsU;                  hsp[2] = hsU + (size_t)NU * DD;
    hsp[3] = hsU + 2ull * NU * DD; hsp[6] = hsU + 3ull * NU * DD;
    hsp[1] = hsA;                  hsp[4] = hsA + (size_t)NA * DD;
    hsp[5] = hsC;                  hsp[7] = hsC + (size_t)NC * DD;

    // CSR config
    EPtrs ep;
    CsrCfg cfg;
    int maxE = 0;
    {
        int acc = 0, eb = 0;
        cfg.bstart[0] = 0;
        for (int t = 0; t < 8; t++) {
            int E = in_sizes[8 + t] / 2;
            ep.p[t]  = (const int*)d_in[8 + t];
            cfg.E[t] = E;
            cfg.n[t] = sizes[dtp[t]] + 1;
            cfg.nb[t] = (cfg.n[t] + 1023) / 1024;
            acc += cfg.nb[t];
            cfg.bstart[t + 1] = acc;
            cfg.eb[t] = eb;
            eb += E;
            if (E > maxE) maxE = E;
        }
    }

    const float* xin[3] = {x_user, x_article, x_cat};
    float* xp[3] = {xu, xa, xc};

    auto mkAgg = [&](int t) {
        AggT T;
        T.off  = offb + t * (NU + 1);
        T.srcs = srcsb + cfg.eb[t];
        T.hs   = hsp[t];
        T.as   = as4 + (size_t)t * NU;
        T.ad   = ad4 + (size_t)t * NU;
        return T;
    };
    Ptr4 adU{ad4 + 1ull * NU, ad4 + 2ull * NU, ad4 + 3ull * NU, ad4 + 7ull * NU};
    Ptr4 adA{ad4 + 0ull * NU, ad4 + 5ull * NU, nullptr, nullptr};
    Ptr4 adC{ad4 + 4ull * NU, ad4 + 6ull * NU, nullptr, nullptr};
    Ptr4 adN{nullptr, nullptr, nullptr, nullptr};

    compute_v_k<<<16, 256, 0, s>>>(Wdst, att_dst, vdst);   // launch 1

    for (int l = 0; l < LL; l++) {
        // gemms (t4,t6 dead at l=1); ad fused into t5 (cat), t1 (article), t0 (user)
        const int gorder0[8] = {5, 7, 4, 1, 0, 2, 3, 6};
        const int gorder1[6] = {5, 7, 1, 0, 2, 3};
        const int* go = (l == 0) ? gorder0 : gorder1;
        int ng = (l == 0) ? 8 : 6;
        for (int gi = 0; gi < ng; gi++) {
            int t = go[gi];
            int S = stp[t];
            int Ns = sizes[S];
            int lt = l * 8 + t;
            const float* xsrc = (l == 0) ? xin[S] : xp[S];
            int nt = 0; int4 adt = make_int4(0, 0, 0, 0); Ptr4 adp = adN;
            if (t == 0) { nt = 4; adt = make_int4(l * 8 + 1, l * 8 + 2, l * 8 + 3, l * 8 + 7); adp = adU; }
            if (t == 1) { nt = 2; adt = make_int4(l * 8 + 0, l * 8 + 5, 0, 0); adp = adA; }
            if (t == 5 && l == 0) { nt = 2; adt = make_int4(4, 6, 0, 0); adp = adC; }
            gemm5_k<<<(Ns + 63) / 64, 256, 0, s>>>(
                xsrc, Wsrc + (size_t)lt * 4096, att_src + (size_t)lt * 64,
                hsp[t], as4 + (size_t)t * NU, Ns, vdst, adt, nt, adp);
        }

        if (l == 0) {
            cudaMemsetAsync(curb, 0, (size_t)8 * (NU + 1) * 4, s);
            hist_all_k<<<dim3((maxE + 255) / 256, 8), 256, 0, s>>>(ep, cfg, curb);
            scan1_all_k<<<cfg.bstart[8], 1024, 0, s>>>(curb, cfg, offb, bsum);
            scan2_all_k<<<8, 256, 0, s>>>(bsum, cfg);
            scan3_all_k<<<cfg.bstart[8], 1024, 0, s>>>(offb, cfg, bsum);
            cudaMemcpyAsync(curb, offb, (size_t)8 * (NU + 1) * 4,
                            cudaMemcpyDeviceToDevice, s);
            scatter_all_k<<<dim3((maxE + 255) / 256, 8), 256, 0, s>>>(ep, cfg, curb, srcsb);
        }

        if (l == 0)
            agg_cat_k<<<Nc, 256, 0, s>>>(mkAgg(4), mkAgg(6), bias, 4, 6, l, xc);
        agg_multi_k<<<(Na + 3) / 4, 256, 0, s>>>(
            mkAgg(0), mkAgg(5), mkAgg(0), mkAgg(0), 2,
            bias, make_int4(0, 5, 0, 0), l,
            l == 0 ? xa : nullptr, acc_a, l == 0 ? x_article : nullptr, Na);
        agg_multi_k<<<(Nu + 3) / 4, 256, 0, s>>>(
            mkAgg(1), mkAgg(2), mkAgg(3), mkAgg(7), 4,
            bias, make_int4(1, 2, 3, 7), l,
            l == 0 ? xu : nullptr, acc_u, l == 0 ? x_user : nullptr, Nu);
    }
}

// round 9
// speedup vs baseline: 1.3497x; 1.3497x over previous
#include <cuda_runtime.h>
#include <cuda_bf16.h>
#include <math_constants.h>

#define NU 200000
#define NA 100000
#define NC 500
#define DD 64
#define HH 4
#define LL 2
#define ETOT 4200000

typedef unsigned long long ull;

#define FMA_F32X2(acc, a, b) \
    asm("fma.rn.f32x2 %0, %1, %2, %0;" : "+l"(acc) : "l"(a), "l"(b))

// ---------------- scratch (device globals; no allocation) -------------------
__device__ float  g_hsU[4][NU * DD];
__device__ float  g_hsA[2][NA * DD];
__device__ float  g_hsC[2][NC * DD];
__device__ float4 g_as [8][NU];
__device__ float4 g_ad [8][NU];
__device__ float  g_xu [NU * DD];
__device__ float  g_xa [NA * DD];
__device__ float  g_xc [NC * DD];
__device__ float  g_vdst[LL * 8 * DD * HH];
__device__ int    g_off [8 * (NU + 1)];
__device__ int    g_cur [8 * (NU + 1)];
__device__ int    g_srcs[ETOT];
__device__ int    g_bsum[2048];

__device__ __forceinline__ float lrelu(float x, float s) { return x > 0.f ? x : s * x; }
__device__ __forceinline__ float pick(float4 v, int h) {
    return h == 0 ? v.x : h == 1 ? v.y : h == 2 ? v.z : v.w;
}

struct EPtrs  { const int* p[8]; };
struct CsrCfg { int E[8]; int n[8]; int nb[8]; int bstart[9]; int eb[8]; };
struct Ptr4   { float4 *p0, *p1, *p2, *p3; };

// ---------------- batched CSR build -----------------------------------------
__global__ void hist_all_k(EPtrs ep, CsrCfg cfg, int* __restrict__ cnt) {
    int t = blockIdx.y;
    int e = blockIdx.x * 256 + threadIdx.x;
    if (e < cfg.E[t]) atomicAdd(&cnt[t * (NU + 1) + ep.p[t][cfg.E[t] + e]], 1);
}

__global__ void scan1_all_k(const int* __restrict__ cnt, CsrCfg cfg,
                            int* __restrict__ off, int* __restrict__ bsum) {
    __shared__ int sh[1024];
    int bid = blockIdx.x;
    int t = 0;
#pragma unroll
    for (int k = 0; k < 8; k++) if (bid >= cfg.bstart[k + 1]) t = k + 1;
    int lb = bid - cfg.bstart[t];
    int tid = threadIdx.x;
    int it = lb * 1024 + tid;
    int n = cfg.n[t];
    int v = (it < n) ? cnt[t * (NU + 1) + it] : 0;
    sh[tid] = v; __syncthreads();
#pragma unroll
    for (int d = 1; d < 1024; d <<= 1) {
        int tv = (tid >= d) ? sh[tid - d] : 0;
        __syncthreads();
        sh[tid] += tv;
        __syncthreads();
    }
    if (it < n) off[t * (NU + 1) + it] = sh[tid] - v;
    if (tid == 1023) bsum[t * 256 + lb] = sh[1023];
}

__global__ void scan2_all_k(int* __restrict__ bsum, CsrCfg cfg) {
    __shared__ int sh[256];
    int t = blockIdx.x, tid = threadIdx.x;
    int nb = cfg.nb[t];
    int v = (tid < nb) ? bsum[t * 256 + tid] : 0;
    sh[tid] = v; __syncthreads();
#pragma unroll
    for (int d = 1; d < 256; d <<= 1) {
        int tv = (tid >= d) ? sh[tid - d] : 0;
        __syncthreads();
        sh[tid] += tv;
        __syncthreads();
    }
    if (tid < nb) bsum[t * 256 + tid] = sh[tid] - v;
}

__global__ void scan3_all_k(int* __restrict__ off, CsrCfg cfg,
                            const int* __restrict__ bsum) {
    int bid = blockIdx.x;
    int t = 0;
#pragma unroll
    for (int k = 0; k < 8; k++) if (bid >= cfg.bstart[k + 1]) t = k + 1;
    int lb = bid - cfg.bstart[t];
    int it = lb * 1024 + threadIdx.x;
    if (it < cfg.n[t]) off[t * (NU + 1) + it] += bsum[t * 256 + lb];
}

__global__ void scatter_all_k(EPtrs ep, CsrCfg cfg, int* __restrict__ cur,
                              int* __restrict__ srcs) {
    int t = blockIdx.y;
    int e = blockIdx.x * 256 + threadIdx.x;
    if (e >= cfg.E[t]) return;
    int c = ep.p[t][cfg.E[t] + e];
    int pos = atomicAdd(&cur[t * (NU + 1) + c], 1);
    srcs[cfg.eb[t] + pos] = ep.p[t][e];
}

// ---------------- dense precompute ------------------------------------------
__global__ void compute_v_k(const float* __restrict__ W, const float* __restrict__ att,
                            float* __restrict__ v) {
    int idx = blockIdx.x * blockDim.x + threadIdx.x;
    if (idx >= LL * 8 * DD * HH) return;
    int lt = idx >> 8, k = (idx >> 2) & 63, h = idx & 3;
    const float* Wr = W + (lt * 64 + k) * 64 + h * 16;
    const float* ar = att + lt * 64 + h * 16;
    float s = 0.f;
#pragma unroll
    for (int c = 0; c < 16; c++) s += Wr[c] * ar[c];
    v[idx] = s;
}

// hs = x @ W (64x64): K in quads, LDS.128 loads, f32x2 FMA. (R7-proven gemm4)
__global__ __launch_bounds__(256, 3) void gemm4_k(
        const float* __restrict__ x, const float* __restrict__ W,
        const float* __restrict__ att, float* __restrict__ hs,
        float4* __restrict__ as_, int N) {
    __shared__ __align__(16) float  Xs[64][68];
    __shared__ __align__(16) float4 Wq[16][72];
    int tid  = threadIdx.x;
    int base = blockIdx.x * 64;
    int nrows = N - base; if (nrows > 64) nrows = 64;

    for (int idx = tid; idx < 1024; idx += 256) {
        int kq = idx >> 6, j = idx & 63;
        int p = j + (j >> 3);
        Wq[kq][p] = make_float4(W[(4 * kq + 0) * 64 + j], W[(4 * kq + 1) * 64 + j],
                                W[(4 * kq + 2) * 64 + j], W[(4 * kq + 3) * 64 + j]);
    }
    for (int idx = tid; idx < 1024; idx += 256) {
        int row = idx >> 4, kq = idx & 15;
        float4 v = (row < nrows) ? *(const float4*)&x[(size_t)(base + row) * 64 + kq * 4]
                                 : make_float4(0.f, 0.f, 0.f, 0.f);
        *(float4*)&Xs[row][kq * 4] = v;
    }
    __syncthreads();

    int tx = tid & 15, ty = tid >> 4;
    int pcol[4];
#pragma unroll
    for (int c = 0; c < 4; c++) {
        int col = tx + 16 * c;
        pcol[c] = col + (col >> 3);
    }

    ull acc[4][4];
#pragma unroll
    for (int r = 0; r < 4; r++)
#pragma unroll
        for (int c = 0; c < 4; c++) acc[r][c] = 0ull;

#pragma unroll
    for (int kq = 0; kq < 16; kq++) {
        ulonglong2 a[4], b[4];
#pragma unroll
        for (int r = 0; r < 4; r++)
            a[r] = *(const ulonglong2*)&Xs[ty * 4 + r][kq * 4];
#pragma unroll
        for (int c = 0; c < 4; c++)
            b[c] = *(const ulonglong2*)&Wq[kq][pcol[c]];
#pragma unroll
        for (int r = 0; r < 4; r++)
#pragma unroll
            for (int c = 0; c < 4; c++) {
                FMA_F32X2(acc[r][c], a[r].x, b[c].x);
                FMA_F32X2(acc[r][c], a[r].y, b[c].y);
            }
    }

    float s[4][4];
#pragma unroll
    for (int r = 0; r < 4; r++)
#pragma unroll
        for (int c = 0; c < 4; c++) {
            float2 v = *(float2*)&acc[r][c];
            s[r][c] = v.x + v.y;
        }

#pragma unroll
    for (int r = 0; r < 4; r++) {
        int row = ty * 4 + r;
        if (row < nrows) {
            float* hp = &hs[(size_t)(base + row) * 64 + tx];
#pragma unroll
            for (int c = 0; c < 4; c++) hp[16 * c] = s[r][c];
        }
    }

    float attv[4];
#pragma unroll
    for (int c = 0; c < 4; c++) attv[c] = att[tx + 16 * c];
    float p[4][4];
#pragma unroll
    for (int r = 0; r < 4; r++)
#pragma unroll
        for (int c = 0; c < 4; c++) p[r][c] = s[r][c] * attv[c];
#pragma unroll
    for (int mask = 1; mask < 16; mask <<= 1)
#pragma unroll
        for (int r = 0; r < 4; r++)
#pragma unroll
            for (int c = 0; c < 4; c++)
                p[r][c] += __shfl_xor_sync(0xffffffffu, p[r][c], mask);
    if (tx == 0) {
#pragma unroll
        for (int r = 0; r < 4; r++) {
            int row = ty * 4 + r;
            if (row < nrows)
                as_[base + row] = make_float4(p[r][0], p[r][1], p[r][2], p[r][3]);
        }
    }
}

// ---------------- fused dst scores: ad for up to 4 incoming types ------------
__global__ void ad_multi_k(const float* __restrict__ x, const float* __restrict__ vdst,
                           int4 tids, int nt, int l, Ptr4 ad, int N) {
    __shared__ __align__(16) float xs[64][68];
    __shared__ __align__(16) float vsm[64][4][4];   // [k][h][ti]
    __shared__ __align__(16) float res[64][16];     // [n][ti*4+h]
    int tid  = threadIdx.x;
    int base = blockIdx.x * 64;
    int nrows = N - base; if (nrows > 64) nrows = 64;

    for (int idx = tid; idx < 1024; idx += 256) {
        int k = idx >> 4, h = (idx >> 2) & 3, ti = idx & 3;
        int t = ti == 0 ? tids.x : ti == 1 ? tids.y : ti == 2 ? tids.z : tids.w;
        vsm[k][h][ti] = (ti < nt) ? vdst[(size_t)(l * 8 + t) * 256 + k * 4 + h] : 0.f;
    }
    for (int idx = tid; idx < 1024; idx += 256) {
        int row = idx >> 4, kq = idx & 15;
        float4 v = (row < nrows) ? *(const float4*)&x[(size_t)(base + row) * 64 + kq * 4]
                                 : make_float4(0.f, 0.f, 0.f, 0.f);
        *(float4*)&xs[row][kq * 4] = v;
    }
    __syncthreads();

    int n = tid >> 2, h = tid & 3;
    float s0 = 0.f, s1 = 0.f, s2 = 0.f, s3 = 0.f;
#pragma unroll
    for (int kq = 0; kq < 16; kq++) {
        float4 xv = *(const float4*)&xs[n][kq * 4];
        float xa[4] = {xv.x, xv.y, xv.z, xv.w};
#pragma unroll
        for (int kk = 0; kk < 4; kk++) {
            float4 vv = *(const float4*)&vsm[kq * 4 + kk][h][0];
            s0 += xa[kk] * vv.x;
            s1 += xa[kk] * vv.y;
            s2 += xa[kk] * vv.z;
            s3 += xa[kk] * vv.w;
        }
    }
    res[n][0 * 4 + h] = s0;
    res[n][1 * 4 + h] = s1;
    res[n][2 * 4 + h] = s2;
    res[n][3 * 4 + h] = s3;
    __syncthreads();

    for (int idx = tid; idx < 256; idx += 256) {
        int ti = idx & 3, n2 = idx >> 2;
        if (ti < nt && n2 < nrows) {
            float4 v = *(const float4*)&res[n2][ti * 4];
            float4* dst = ti == 0 ? ad.p0 : ti == 1 ? ad.p1 : ti == 2 ? ad.p2 : ad.p3;
            dst[base + n2] = v;
        }
    }
}

// ---------------- fused multi-type aggregation + epilogue --------------------
struct AggT {
    const int*    off;
    const int*    srcs;
    const float*  hs;
    const float4* as;
    const float4* ad;
};

// Order-independent softmax (no max shift — logits are O(0.1)). Simple serial
// loop: occupancy hides the gather latency (R8 showed manual unroll regresses).
__device__ __forceinline__ float proc_type(const AggT& T, int g, int j, int h) {
    int s0 = T.off[g], s1 = T.off[g + 1];
    if (s0 == s1) return 0.f;
    float b = pick(T.ad[g], h);
    float d = 0.f, acc = 0.f;
    for (int s = s0; s < s1; s++) {
        int r = T.srcs[s];
        float4 a4 = T.as[r];
        float hv = T.hs[(size_t)r * 64 + j];
        float e = lrelu(pick(a4, h) + b, 0.2f);
        float pw = __expf(e);
        d += pw;
        acc += hv * pw;
    }
    return acc / d;
}

__global__ void agg_multi_k(AggT a0, AggT a1, AggT a2, AggT a3, int nt,
                            const float* __restrict__ bias, int4 tids, int l,
                            float* __restrict__ xout, float* __restrict__ accv,
                            const float* __restrict__ xin, int Nd) {
    int g = blockIdx.x * 4 + (threadIdx.x >> 6);
    if (g >= Nd) return;
    int j = threadIdx.x & 63, h = j >> 4;

    float total = proc_type(a0, g, j, h);
    if (nt > 1) total += proc_type(a1, g, j, h);
    if (nt > 2) total += proc_type(a2, g, j, h);
    if (nt > 3) total += proc_type(a3, g, j, h);

    float bs = bias[(size_t)(l * 8 + tids.x) * 64 + j];
    if (nt > 1) bs += bias[(size_t)(l * 8 + tids.y) * 64 + j];
    if (nt > 2) bs += bias[(size_t)(l * 8 + tids.z) * 64 + j];
    if (nt > 3) bs += bias[(size_t)(l * 8 + tids.w) * 64 + j];

    float v = total + bs;
    v = v > 0.f ? v : 0.01f * v;
    size_t o = (size_t)g * 64 + j;
    if (xout) xout[o] = v;
    if (accv) accv[o] = xin ? (xin[o] + v) : ((accv[o] + v) * (1.f / 3.f));
}

// category dst: block per node, 4 chunks, 2 types, fused epilogue (layer 0 only)
__device__ float proc_cat_type(const AggT& T, int g, int tid, int chunk, int j, int h,
                               float sd[4][4], float sacc[4][64]) {
    int s0 = T.off[g], s1 = T.off[g + 1];
    float b = pick(T.ad[g], h);
    float d = 0.f, acc = 0.f;
    for (int s = s0 + chunk; s < s1; s += 4) {
        int r = T.srcs[s];
        float4 a4 = T.as[r];
        float hv = T.hs[(size_t)r * 64 + j];
        float pw = __expf(lrelu(pick(a4, h) + b, 0.2f));
        d += pw;
        acc += hv * pw;
    }
    if ((j & 15) == 0) sd[chunk][h] = d;
    sacc[chunk][j] = acc;
    __syncthreads();
    float out = 0.f;
    if (tid < 64) {
        int hh = tid >> 4;
        float dg = sd[0][hh] + sd[1][hh] + sd[2][hh] + sd[3][hh];
        out = (sacc[0][tid] + sacc[1][tid] + sacc[2][tid] + sacc[3][tid]) / (dg + 1e-16f);
    }
    __syncthreads();
    return out;
}

__global__ void agg_cat_k(AggT a0, AggT a1, const float* __restrict__ bias,
                          int t0, int t1, int l, float* __restrict__ xout) {
    int g = blockIdx.x;
    int tid = threadIdx.x, chunk = tid >> 6, j = tid & 63, h = j >> 4;
    __shared__ float sd[4][4], sacc[4][64];
    float tot = proc_cat_type(a0, g, tid, chunk, j, h, sd, sacc);
    tot      += proc_cat_type(a1, g, tid, chunk, j, h, sd, sacc);
    if (tid < 64) {
        float v = tot + bias[(size_t)(l * 8 + t0) * 64 + tid]
                      + bias[(size_t)(l * 8 + t1) * 64 + tid];
        v = v > 0.f ? v : 0.01f * v;
        xout[(size_t)g * 64 + tid] = v;
    }
}

// ---------------- host orchestration ----------------------------------------
extern "C" void kernel_launch(void* const* d_in, const int* in_sizes, int n_in,
                              void* d_out, int out_size) {
    const float* x_user    = (const float*)d_in[0];
    const float* x_article = (const float*)d_in[1];
    const float* x_cat     = (const float*)d_in[2];
    const float* Wsrc      = (const float*)d_in[3];
    const float* Wdst      = (const float*)d_in[4];
    const float* att_src   = (const float*)d_in[5];
    const float* att_dst   = (const float*)d_in[6];
    const float* bias      = (const float*)d_in[7];

    int Nu = in_sizes[0] / DD, Na = in_sizes[1] / DD, Nc = in_sizes[2] / DD;

    float *xu, *xa, *xc, *vdst;
    float4 *as4, *ad4;
    int *offb, *curb, *srcsb, *bsum;
    float *hsU, *hsA, *hsC;
    cudaGetSymbolAddress((void**)&hsU,  g_hsU);
    cudaGetSymbolAddress((void**)&hsA,  g_hsA);
    cudaGetSymbolAddress((void**)&hsC,  g_hsC);
    cudaGetSymbolAddress((void**)&as4,  g_as);
    cudaGetSymbolAddress((void**)&ad4,  g_ad);
    cudaGetSymbolAddress((void**)&xu,   g_xu);
    cudaGetSymbolAddress((void**)&xa,   g_xa);
    cudaGetSymbolAddress((void**)&xc,   g_xc);
    cudaGetSymbolAddress((void**)&vdst, g_vdst);
    cudaGetSymbolAddress((void**)&offb, g_off);
    cudaGetSymbolAddress((void**)&curb, g_cur);
    cudaGetSymbolAddress((void**)&srcsb, g_srcs);
    cudaGetSymbolAddress((void**)&bsum, g_bsum);

    cudaStream_t s = 0;
    float* acc_u = (float*)d_out;
    float* acc_a = (float*)d_out + (size_t)Nu * DD;

    int sizes[3] = {Nu, Na, Nc};
    const int stp[8] = {0, 1, 0, 0, 1, 2, 0, 2};
    const int dtp[8] = {1, 0, 0, 0, 2, 1, 2, 0};
    float* hsp[8];
    hsp[0] = hsU;                  hsp[2] = hsU + (size_t)NU * DD;
    hsp[3] = hsU + 2ull * NU * DD; hsp[6] = hsU + 3ull * NU * DD;
    hsp[1] = hsA;                  hsp[4] = hsA + (size_t)NA * DD;
    hsp[5] = hsC;                  hsp[7] = hsC + (size_t)NC * DD;

    // CSR config
    EPtrs ep;
    CsrCfg cfg;
    int maxE = 0;
    {
        int acc = 0, eb = 0;
        cfg.bstart[0] = 0;
        for (int t = 0; t < 8; t++) {
            int E = in_sizes[8 + t] / 2;
            ep.p[t]  = (const int*)d_in[8 + t];
            cfg.E[t] = E;
            cfg.n[t] = sizes[dtp[t]] + 1;
            cfg.nb[t] = (cfg.n[t] + 1023) / 1024;
            acc += cfg.nb[t];
            cfg.bstart[t + 1] = acc;
            cfg.eb[t] = eb;
            eb += E;
            if (E > maxE) maxE = E;
        }
    }

    const float* xin[3] = {x_user, x_article, x_cat};
    float* xp[3] = {xu, xa, xc};

    auto mkAgg = [&](int t) {
        AggT T;
        T.off  = offb + t * (NU + 1);
        T.srcs = srcsb + cfg.eb[t];
        T.hs   = hsp[t];
        T.as   = as4 + (size_t)t * NU;
        T.ad   = ad4 + (size_t)t * NU;
        return T;
    };
    Ptr4 adU{ad4 + 1ull * NU, ad4 + 2ull * NU, ad4 + 3ull * NU, ad4 + 7ull * NU};
    Ptr4 adA{ad4 + 0ull * NU, ad4 + 5ull * NU, ad4, ad4};
    Ptr4 adC{ad4 + 4ull * NU, ad4 + 6ull * NU, ad4, ad4};

    compute_v_k<<<16, 256, 0, s>>>(Wdst, att_dst, vdst);   // launch 1

    for (int l = 0; l < LL; l++) {
        // gemms; t4,t6 dead at l=1 (their hs only feeds category agg)
        const int gorder0[8] = {5, 7, 4, 1, 0, 2, 3, 6};
        const int gorder1[6] = {5, 7, 1, 0, 2, 3};
        const int* go = (l == 0) ? gorder0 : gorder1;
        int ng = (l == 0) ? 8 : 6;
        for (int gi = 0; gi < ng; gi++) {
            int t = go[gi];
            int S = stp[t];
            int Ns = sizes[S];
            int lt = l * 8 + t;
            const float* xsrc = (l == 0) ? xin[S] : xp[S];
            gemm4_k<<<(Ns + 63) / 64, 256, 0, s>>>(
                xsrc, Wsrc + (size_t)lt * 4096, att_src + (size_t)lt * 64,
                hsp[t], as4 + (size_t)t * NU, Ns);
        }

        // dst scores (separate kernels — fusion into gemm regressed in R8)
        {
            const float* xd = (l == 0) ? xin[0] : xp[0];    // user dst: t=1,2,3,7
            ad_multi_k<<<(Nu + 63) / 64, 256, 0, s>>>(xd, vdst, make_int4(1, 2, 3, 7), 4, l, adU, Nu);
        }
        {
            const float* xd = (l == 0) ? xin[1] : xp[1];    // article dst: t=0,5
            ad_multi_k<<<(Na + 63) / 64, 256, 0, s>>>(xd, vdst, make_int4(0, 5, 0, 0), 2, l, adA, Na);
        }
        if (l == 0) {                                        // category dst: t=4,6
            ad_multi_k<<<(Nc + 63) / 64, 256, 0, s>>>(xin[2], vdst, make_int4(4, 6, 0, 0), 2, l, adC, Nc);
        }

        if (l == 0) {
            cudaMemsetAsync(curb, 0, (size_t)8 * (NU + 1) * 4, s);
            hist_all_k<<<dim3((maxE + 255) / 256, 8), 256, 0, s>>>(ep, cfg, curb);
            scan1_all_k<<<cfg.bstart[8], 1024, 0, s>>>(curb, cfg, offb, bsum);
            scan2_all_k<<<8, 256, 0, s>>>(bsum, cfg);
            scan3_all_k<<<cfg.bstart[8], 1024, 0, s>>>(offb, cfg, bsum);
            cudaMemcpyAsync(curb, offb, (size_t)8 * (NU + 1) * 4,
                            cudaMemcpyDeviceToDevice, s);
            scatter_all_k<<<dim3((maxE + 255) / 256, 8), 256, 0, s>>>(ep, cfg, curb, srcsb);
        }

        if (l == 0)
            agg_cat_k<<<Nc, 256, 0, s>>>(mkAgg(4), mkAgg(6), bias, 4, 6, l, xc);
        agg_multi_k<<<(Na + 3) / 4, 256, 0, s>>>(
            mkAgg(0), mkAgg(5), mkAgg(0), mkAgg(0), 2,
            bias, make_int4(0, 5, 0, 0), l,
            l == 0 ? xa : nullptr, acc_a, l == 0 ? x_article : nullptr, Na);
        agg_multi_k<<<(Nu + 3) / 4, 256, 0, s>>>(
            mkAgg(1), mkAgg(2), mkAgg(3), mkAgg(7), 4,
            bias, make_int4(1, 2, 3, 7), l,
            l == 0 ? xu : nullptr, acc_u, l == 0 ? x_user : nullptr, Nu);
    }
}

// round 10
// speedup vs baseline: 1.8506x; 1.3712x over previous
#include <cuda_runtime.h>
#include <cuda_bf16.h>
#include <math_constants.h>

#define NU 200000
#define NA 100000
#define NC 500
#define DD 64
#define HH 4
#define LL 2
#define ETOT 4200000

typedef unsigned long long ull;

#define FMA_F32X2(acc, a, b) \
    asm("fma.rn.f32x2 %0, %1, %2, %0;" : "+l"(acc) : "l"(a), "l"(b))

// ---------------- scratch (device globals; no allocation) -------------------
__device__ float  g_hsU[4][NU * DD];
__device__ float  g_hsA[2][NA * DD];
__device__ float  g_hsC[2][NC * DD];
__device__ float4 g_as [8][NU];
__device__ float4 g_ad [8][NU];
__device__ float  g_xu [NU * DD];
__device__ float  g_xa [NA * DD];
__device__ float  g_xc [NC * DD];
__device__ float  g_vdst[LL * 8 * DD * HH];
__device__ int    g_off [8 * (NU + 1)];
__device__ int    g_cur [8 * (NU + 1)];
__device__ int    g_srcs[ETOT];
__device__ int    g_bsum[2048];

__device__ __forceinline__ float lrelu(float x, float s) { return x > 0.f ? x : s * x; }
__device__ __forceinline__ float pick(float4 v, int h) {
    return h == 0 ? v.x : h == 1 ? v.y : h == 2 ? v.z : v.w;
}

struct EPtrs  { const int* p[8]; };
struct CsrCfg { int E[8]; int n[8]; int nb[8]; int bstart[9]; int eb[8]; };
struct Ptr4   { float4 *p0, *p1, *p2, *p3; };

// ---------------- batched CSR build -----------------------------------------
__global__ void hist_all_k(EPtrs ep, CsrCfg cfg, int* __restrict__ cnt) {
    int t = blockIdx.y;
    int e = blockIdx.x * 256 + threadIdx.x;
    if (e < cfg.E[t]) atomicAdd(&cnt[t * (NU + 1) + ep.p[t][cfg.E[t] + e]], 1);
}

__global__ void scan1_all_k(const int* __restrict__ cnt, CsrCfg cfg,
                            int* __restrict__ off, int* __restrict__ bsum) {
    __shared__ int sh[1024];
    int bid = blockIdx.x;
    int t = 0;
#pragma unroll
    for (int k = 0; k < 8; k++) if (bid >= cfg.bstart[k + 1]) t = k + 1;
    int lb = bid - cfg.bstart[t];
    int tid = threadIdx.x;
    int it = lb * 1024 + tid;
    int n = cfg.n[t];
    int v = (it < n) ? cnt[t * (NU + 1) + it] : 0;
    sh[tid] = v; __syncthreads();
#pragma unroll
    for (int d = 1; d < 1024; d <<= 1) {
        int tv = (tid >= d) ? sh[tid - d] : 0;
        __syncthreads();
        sh[tid] += tv;
        __syncthreads();
    }
    if (it < n) off[t * (NU + 1) + it] = sh[tid] - v;
    if (tid == 1023) bsum[t * 256 + lb] = sh[1023];
}

__global__ void scan2_all_k(int* __restrict__ bsum, CsrCfg cfg) {
    __shared__ int sh[256];
    int t = blockIdx.x, tid = threadIdx.x;
    int nb = cfg.nb[t];
    int v = (tid < nb) ? bsum[t * 256 + tid] : 0;
    sh[tid] = v; __syncthreads();
#pragma unroll
    for (int d = 1; d < 256; d <<= 1) {
        int tv = (tid >= d) ? sh[tid - d] : 0;
        __syncthreads();
        sh[tid] += tv;
        __syncthreads();
    }
    if (tid < nb) bsum[t * 256 + tid] = sh[tid] - v;
}

__global__ void scan3_all_k(int* __restrict__ off, CsrCfg cfg,
                            const int* __restrict__ bsum) {
    int bid = blockIdx.x;
    int t = 0;
#pragma unroll
    for (int k = 0; k < 8; k++) if (bid >= cfg.bstart[k + 1]) t = k + 1;
    int lb = bid - cfg.bstart[t];
    int it = lb * 1024 + threadIdx.x;
    if (it < cfg.n[t]) off[t * (NU + 1) + it] += bsum[t * 256 + lb];
}

__global__ void scatter_all_k(EPtrs ep, CsrCfg cfg, int* __restrict__ cur,
                              int* __restrict__ srcs) {
    int t = blockIdx.y;
    int e = blockIdx.x * 256 + threadIdx.x;
    if (e >= cfg.E[t]) return;
    int c = ep.p[t][cfg.E[t] + e];
    int pos = atomicAdd(&cur[t * (NU + 1) + c], 1);
    srcs[cfg.eb[t] + pos] = ep.p[t][e];
}

// ---------------- dense precompute ------------------------------------------
__global__ void compute_v_k(const float* __restrict__ W, const float* __restrict__ att,
                            float* __restrict__ v) {
    int idx = blockIdx.x * blockDim.x + threadIdx.x;
    if (idx >= LL * 8 * DD * HH) return;
    int lt = idx >> 8, k = (idx >> 2) & 63, h = idx & 3;
    const float* Wr = W + (lt * 64 + k) * 64 + h * 16;
    const float* ar = att + lt * 64 + h * 16;
    float s = 0.f;
#pragma unroll
    for (int c = 0; c < 16; c++) s += Wr[c] * ar[c];
    v[idx] = s;
}

// hs = x @ W (64x64): K in quads, LDS.128 loads, f32x2 FMA. (R7-proven gemm4)
__global__ __launch_bounds__(256, 3) void gemm4_k(
        const float* __restrict__ x, const float* __restrict__ W,
        const float* __restrict__ att, float* __restrict__ hs,
        float4* __restrict__ as_, int N) {
    __shared__ __align__(16) float  Xs[64][68];
    __shared__ __align__(16) float4 Wq[16][72];
    int tid  = threadIdx.x;
    int base = blockIdx.x * 64;
    int nrows = N - base; if (nrows > 64) nrows = 64;

    for (int idx = tid; idx < 1024; idx += 256) {
        int kq = idx >> 6, j = idx & 63;
        int p = j + (j >> 3);
        Wq[kq][p] = make_float4(W[(4 * kq + 0) * 64 + j], W[(4 * kq + 1) * 64 + j],
                                W[(4 * kq + 2) * 64 + j], W[(4 * kq + 3) * 64 + j]);
    }
    for (int idx = tid; idx < 1024; idx += 256) {
        int row = idx >> 4, kq = idx & 15;
        float4 v = (row < nrows) ? *(const float4*)&x[(size_t)(base + row) * 64 + kq * 4]
                                 : make_float4(0.f, 0.f, 0.f, 0.f);
        *(float4*)&Xs[row][kq * 4] = v;
    }
    __syncthreads();

    int tx = tid & 15, ty = tid >> 4;
    int pcol[4];
#pragma unroll
    for (int c = 0; c < 4; c++) {
        int col = tx + 16 * c;
        pcol[c] = col + (col >> 3);
    }

    ull acc[4][4];
#pragma unroll
    for (int r = 0; r < 4; r++)
#pragma unroll
        for (int c = 0; c < 4; c++) acc[r][c] = 0ull;

#pragma unroll
    for (int kq = 0; kq < 16; kq++) {
        ulonglong2 a[4], b[4];
#pragma unroll
        for (int r = 0; r < 4; r++)
            a[r] = *(const ulonglong2*)&Xs[ty * 4 + r][kq * 4];
#pragma unroll
        for (int c = 0; c < 4; c++)
            b[c] = *(const ulonglong2*)&Wq[kq][pcol[c]];
#pragma unroll
        for (int r = 0; r < 4; r++)
#pragma unroll
            for (int c = 0; c < 4; c++) {
                FMA_F32X2(acc[r][c], a[r].x, b[c].x);
                FMA_F32X2(acc[r][c], a[r].y, b[c].y);
            }
    }

    float s[4][4];
#pragma unroll
    for (int r = 0; r < 4; r++)
#pragma unroll
        for (int c = 0; c < 4; c++) {
            float2 v = *(float2*)&acc[r][c];
            s[r][c] = v.x + v.y;
        }

#pragma unroll
    for (int r = 0; r < 4; r++) {
        int row = ty * 4 + r;
        if (row < nrows) {
            float* hp = &hs[(size_t)(base + row) * 64 + tx];
#pragma unroll
            for (int c = 0; c < 4; c++) hp[16 * c] = s[r][c];
        }
    }

    float attv[4];
#pragma unroll
    for (int c = 0; c < 4; c++) attv[c] = att[tx + 16 * c];
    float p[4][4];
#pragma unroll
    for (int r = 0; r < 4; r++)
#pragma unroll
        for (int c = 0; c < 4; c++) p[r][c] = s[r][c] * attv[c];
#pragma unroll
    for (int mask = 1; mask < 16; mask <<= 1)
#pragma unroll
        for (int r = 0; r < 4; r++)
#pragma unroll
            for (int c = 0; c < 4; c++)
                p[r][c] += __shfl_xor_sync(0xffffffffu, p[r][c], mask);
    if (tx == 0) {
#pragma unroll
        for (int r = 0; r < 4; r++) {
            int row = ty * 4 + r;
            if (row < nrows)
                as_[base + row] = make_float4(p[r][0], p[r][1], p[r][2], p[r][3]);
        }
    }
}

// ---------------- fused dst scores: ad for up to 4 incoming types ------------
__global__ void ad_multi_k(const float* __restrict__ x, const float* __restrict__ vdst,
                           int4 tids, int nt, int l, Ptr4 ad, int N) {
    __shared__ __align__(16) float xs[64][68];
    __shared__ __align__(16) float vsm[64][4][4];   // [k][h][ti]
    __shared__ __align__(16) float res[64][16];     // [n][ti*4+h]
    int tid  = threadIdx.x;
    int base = blockIdx.x * 64;
    int nrows = N - base; if (nrows > 64) nrows = 64;

    for (int idx = tid; idx < 1024; idx += 256) {
        int k = idx >> 4, h = (idx >> 2) & 3, ti = idx & 3;
        int t = ti == 0 ? tids.x : ti == 1 ? tids.y : ti == 2 ? tids.z : tids.w;
        vsm[k][h][ti] = (ti < nt) ? vdst[(size_t)(l * 8 + t) * 256 + k * 4 + h] : 0.f;
    }
    for (int idx = tid; idx < 1024; idx += 256) {
        int row = idx >> 4, kq = idx & 15;
        float4 v = (row < nrows) ? *(const float4*)&x[(size_t)(base + row) * 64 + kq * 4]
                                 : make_float4(0.f, 0.f, 0.f, 0.f);
        *(float4*)&xs[row][kq * 4] = v;
    }
    __syncthreads();

    int n = tid >> 2, h = tid & 3;
    float s0 = 0.f, s1 = 0.f, s2 = 0.f, s3 = 0.f;
#pragma unroll
    for (int kq = 0; kq < 16; kq++) {
        float4 xv = *(const float4*)&xs[n][kq * 4];
        float xa[4] = {xv.x, xv.y, xv.z, xv.w};
#pragma unroll
        for (int kk = 0; kk < 4; kk++) {
            float4 vv = *(const float4*)&vsm[kq * 4 + kk][h][0];
            s0 += xa[kk] * vv.x;
            s1 += xa[kk] * vv.y;
            s2 += xa[kk] * vv.z;
            s3 += xa[kk] * vv.w;
        }
    }
    res[n][0 * 4 + h] = s0;
    res[n][1 * 4 + h] = s1;
    res[n][2 * 4 + h] = s2;
    res[n][3 * 4 + h] = s3;
    __syncthreads();

    for (int idx = tid; idx < 256; idx += 256) {
        int ti = idx & 3, n2 = idx >> 2;
        if (ti < nt && n2 < nrows) {
            float4 v = *(const float4*)&res[n2][ti * 4];
            float4* dst = ti == 0 ? ad.p0 : ti == 1 ? ad.p1 : ti == 2 ? ad.p2 : ad.p3;
            dst[base + n2] = v;
        }
    }
}

// ---------------- fused multi-type aggregation + epilogue --------------------
struct AggT {
    const int*    off;
    const int*    srcs;
    const float*  hs;
    const float4* as;
    const float4* ad;
};

// 16 threads per dst: thread tx owns channel quad [4tx..4tx+3] (one head each).
// Order-independent softmax (no max shift — logits are O(0.1)).
__device__ __forceinline__ float4 proc_type4(const AggT& T, int g, int tx, int h) {
    int s0 = T.off[g], s1 = T.off[g + 1];
    if (s0 == s1) return make_float4(0.f, 0.f, 0.f, 0.f);
    float b = pick(T.ad[g], h);
    float d = 0.f;
    float4 acc = make_float4(0.f, 0.f, 0.f, 0.f);
    for (int s = s0; s < s1; s++) {
        int r = T.srcs[s];
        float a = pick(T.as[r], h);
        float4 hv = *(const float4*)&T.hs[(size_t)r * 64 + tx * 4];
        float pw = __expf(lrelu(a + b, 0.2f));
        d += pw;
        acc.x += hv.x * pw;
        acc.y += hv.y * pw;
        acc.z += hv.z * pw;
        acc.w += hv.w * pw;
    }
    float inv = 1.f / d;
    return make_float4(acc.x * inv, acc.y * inv, acc.z * inv, acc.w * inv);
}

__global__ void agg_multi_k(AggT a0, AggT a1, AggT a2, AggT a3, int nt,
                            const float* __restrict__ bias, int4 tids, int l,
                            float* __restrict__ xout, float* __restrict__ accv,
                            const float* __restrict__ xin, int Nd) {
    int g = blockIdx.x * 16 + (threadIdx.x >> 4);
    if (g >= Nd) return;
    int tx = threadIdx.x & 15, h = tx >> 2;

    float4 t0 = proc_type4(a0, g, tx, h);
    float4 total = t0;
    if (nt > 1) {
        float4 t1 = proc_type4(a1, g, tx, h);
        total.x += t1.x; total.y += t1.y; total.z += t1.z; total.w += t1.w;
    }
    if (nt > 2) {
        float4 t2 = proc_type4(a2, g, tx, h);
        total.x += t2.x; total.y += t2.y; total.z += t2.z; total.w += t2.w;
    }
    if (nt > 3) {
        float4 t3 = proc_type4(a3, g, tx, h);
        total.x += t3.x; total.y += t3.y; total.z += t3.z; total.w += t3.w;
    }

    float4 bs = *(const float4*)&bias[(size_t)(l * 8 + tids.x) * 64 + tx * 4];
    if (nt > 1) {
        float4 b1 = *(const float4*)&bias[(size_t)(l * 8 + tids.y) * 64 + tx * 4];
        bs.x += b1.x; bs.y += b1.y; bs.z += b1.z; bs.w += b1.w;
    }
    if (nt > 2) {
        float4 b2 = *(const float4*)&bias[(size_t)(l * 8 + tids.z) * 64 + tx * 4];
        bs.x += b2.x; bs.y += b2.y; bs.z += b2.z; bs.w += b2.w;
    }
    if (nt > 3) {
        float4 b3 = *(const float4*)&bias[(size_t)(l * 8 + tids.w) * 64 + tx * 4];
        bs.x += b3.x; bs.y += b3.y; bs.z += b3.z; bs.w += b3.w;
    }

    float4 v;
    v.x = total.x + bs.x; v.x = v.x > 0.f ? v.x : 0.01f * v.x;
    v.y = total.y + bs.y; v.y = v.y > 0.f ? v.y : 0.01f * v.y;
    v.z = total.z + bs.z; v.z = v.z > 0.f ? v.z : 0.01f * v.z;
    v.w = total.w + bs.w; v.w = v.w > 0.f ? v.w : 0.01f * v.w;

    size_t o = (size_t)g * 64 + tx * 4;
    if (xout) *(float4*)&xout[o] = v;
    if (accv) {
        float4 av;
        if (xin) {
            float4 xi = *(const float4*)&xin[o];
            av = make_float4(xi.x + v.x, xi.y + v.y, xi.z + v.z, xi.w + v.w);
        } else {
            float4 ao = *(const float4*)&accv[o];
            av = make_float4((ao.x + v.x) * (1.f / 3.f), (ao.y + v.y) * (1.f / 3.f),
                             (ao.z + v.z) * (1.f / 3.f), (ao.w + v.w) * (1.f / 3.f));
        }
        *(float4*)&accv[o] = av;
    }
}

// category dst: block per node, 4 chunks, 2 types, fused epilogue (layer 0 only)
__device__ float proc_cat_type(const AggT& T, int g, int tid, int chunk, int j, int h,
                               float sd[4][4], float sacc[4][64]) {
    int s0 = T.off[g], s1 = T.off[g + 1];
    float b = pick(T.ad[g], h);
    float d = 0.f, acc = 0.f;
    for (int s = s0 + chunk; s < s1; s += 4) {
        int r = T.srcs[s];
        float4 a4 = T.as[r];
        float hv = T.hs[(size_t)r * 64 + j];
        float pw = __expf(lrelu(pick(a4, h) + b, 0.2f));
        d += pw;
        acc += hv * pw;
    }
    if ((j & 15) == 0) sd[chunk][h] = d;
    sacc[chunk][j] = acc;
    __syncthreads();
    float out = 0.f;
    if (tid < 64) {
        int hh = tid >> 4;
        float dg = sd[0][hh] + sd[1][hh] + sd[2][hh] + sd[3][hh];
        out = (sacc[0][tid] + sacc[1][tid] + sacc[2][tid] + sacc[3][tid]) / (dg + 1e-16f);
    }
    __syncthreads();
    return out;
}

__global__ void agg_cat_k(AggT a0, AggT a1, const float* __restrict__ bias,
                          int t0, int t1, int l, float* __restrict__ xout) {
    int g = blockIdx.x;
    int tid = threadIdx.x, chunk = tid >> 6, j = tid & 63, h = j >> 4;
    __shared__ float sd[4][4], sacc[4][64];
    float tot = proc_cat_type(a0, g, tid, chunk, j, h, sd, sacc);
    tot      += proc_cat_type(a1, g, tid, chunk, j, h, sd, sacc);
    if (tid < 64) {
        float v = tot + bias[(size_t)(l * 8 + t0) * 64 + tid]
                      + bias[(size_t)(l * 8 + t1) * 64 + tid];
        v = v > 0.f ? v : 0.01f * v;
        xout[(size_t)g * 64 + tid] = v;
    }
}

// ---------------- host orchestration ----------------------------------------
extern "C" void kernel_launch(void* const* d_in, const int* in_sizes, int n_in,
                              void* d_out, int out_size) {
    const float* x_user    = (const float*)d_in[0];
    const float* x_article = (const float*)d_in[1];
    const float* x_cat     = (const float*)d_in[2];
    const float* Wsrc      = (const float*)d_in[3];
    const float* Wdst      = (const float*)d_in[4];
    const float* att_src   = (const float*)d_in[5];
    const float* att_dst   = (const float*)d_in[6];
    const float* bias      = (const float*)d_in[7];

    int Nu = in_sizes[0] / DD, Na = in_sizes[1] / DD, Nc = in_sizes[2] / DD;

    float *xu, *xa, *xc, *vdst;
    float4 *as4, *ad4;
    int *offb, *curb, *srcsb, *bsum;
    float *hsU, *hsA, *hsC;
    cudaGetSymbolAddress((void**)&hsU,  g_hsU);
    cudaGetSymbolAddress((void**)&hsA,  g_hsA);
    cudaGetSymbolAddress((void**)&hsC,  g_hsC);
    cudaGetSymbolAddress((void**)&as4,  g_as);
    cudaGetSymbolAddress((void**)&ad4,  g_ad);
    cudaGetSymbolAddress((void**)&xu,   g_xu);
    cudaGetSymbolAddress((void**)&xa,   g_xa);
    cudaGetSymbolAddress((void**)&xc,   g_xc);
    cudaGetSymbolAddress((void**)&vdst, g_vdst);
    cudaGetSymbolAddress((void**)&offb, g_off);
    cudaGetSymbolAddress((void**)&curb, g_cur);
    cudaGetSymbolAddress((void**)&srcsb, g_srcs);
    cudaGetSymbolAddress((void**)&bsum, g_bsum);

    cudaStream_t s = 0;
    float* acc_u = (float*)d_out;
    float* acc_a = (float*)d_out + (size_t)Nu * DD;

    int sizes[3] = {Nu, Na, Nc};
    const int stp[8] = {0, 1, 0, 0, 1, 2, 0, 2};
    const int dtp[8] = {1, 0, 0, 0, 2, 1, 2, 0};
    float* hsp[8];
    hsp[0] = hsU;                  hsp[2] = hsU + (size_t)NU * DD;
    hsp[3] = hsU + 2ull * NU * DD; hsp[6] = hsU + 3ull * NU * DD;
    hsp[1] = hsA;                  hsp[4] = hsA + (size_t)NA * DD;
    hsp[5] = hsC;                  hsp[7] = hsC + (size_t)NC * DD;

    // CSR config
    EPtrs ep;
    CsrCfg cfg;
    int maxE = 0;
    {
        int acc = 0, eb = 0;
        cfg.bstart[0] = 0;
        for (int t = 0; t < 8; t++) {
            int E = in_sizes[8 + t] / 2;
            ep.p[t]  = (const int*)d_in[8 + t];
            cfg.E[t] = E;
            cfg.n[t] = sizes[dtp[t]] + 1;
            cfg.nb[t] = (cfg.n[t] + 1023) / 1024;
            acc += cfg.nb[t];
            cfg.bstart[t + 1] = acc;
            cfg.eb[t] = eb;
            eb += E;
            if (E > maxE) maxE = E;
        }
    }

    const float* xin[3] = {x_user, x_article, x_cat};
    float* xp[3] = {xu, xa, xc};

    auto mkAgg = [&](int t) {
        AggT T;
        T.off  = offb + t * (NU + 1);
        T.srcs = srcsb + cfg.eb[t];
        T.hs   = hsp[t];
        T.as   = as4 + (size_t)t * NU;
        T.ad   = ad4 + (size_t)t * NU;
        return T;
    };
    Ptr4 adU{ad4 + 1ull * NU, ad4 + 2ull * NU, ad4 + 3ull * NU, ad4 + 7ull * NU};
    Ptr4 adA{ad4 + 0ull * NU, ad4 + 5ull * NU, ad4, ad4};
    Ptr4 adC{ad4 + 4ull * NU, ad4 + 6ull * NU, ad4, ad4};

    compute_v_k<<<16, 256, 0, s>>>(Wdst, att_dst, vdst);   // launch 1

    for (int l = 0; l < LL; l++) {
        // gemms; t4,t6 dead at l=1 (their hs only feeds category agg)
        const int gorder0[8] = {5, 7, 4, 1, 0, 2, 3, 6};
        const int gorder1[6] = {5, 7, 1, 0, 2, 3};
        const int* go = (l == 0) ? gorder0 : gorder1;
        int ng = (l == 0) ? 8 : 6;
        for (int gi = 0; gi < ng; gi++) {
            int t = go[gi];
            int S = stp[t];
            int Ns = sizes[S];
            int lt = l * 8 + t;
            const float* xsrc = (l == 0) ? xin[S] : xp[S];
            gemm4_k<<<(Ns + 63) / 64, 256, 0, s>>>(
                xsrc, Wsrc + (size_t)lt * 4096, att_src + (size_t)lt * 64,
                hsp[t], as4 + (size_t)t * NU, Ns);
        }

        // dst scores (separate kernels — fusion into gemm regressed in R8)
        {
            const float* xd = (l == 0) ? xin[0] : xp[0];    // user dst: t=1,2,3,7
            ad_multi_k<<<(Nu + 63) / 64, 256, 0, s>>>(xd, vdst, make_int4(1, 2, 3, 7), 4, l, adU, Nu);
        }
        {
            const float* xd = (l == 0) ? xin[1] : xp[1];    // article dst: t=0,5
            ad_multi_k<<<(Na + 63) / 64, 256, 0, s>>>(xd, vdst, make_int4(0, 5, 0, 0), 2, l, adA, Na);
        }
        if (l == 0) {                                        // category dst: t=4,6
            ad_multi_k<<<(Nc + 63) / 64, 256, 0, s>>>(xin[2], vdst, make_int4(4, 6, 0, 0), 2, l, adC, Nc);
        }

        if (l == 0) {
            cudaMemsetAsync(curb, 0, (size_t)8 * (NU + 1) * 4, s);
            hist_all_k<<<dim3((maxE + 255) / 256, 8), 256, 0, s>>>(ep, cfg, curb);
            scan1_all_k<<<cfg.bstart[8], 1024, 0, s>>>(curb, cfg, offb, bsum);
            scan2_all_k<<<8, 256, 0, s>>>(bsum, cfg);
            scan3_all_k<<<cfg.bstart[8], 1024, 0, s>>>(offb, cfg, bsum);
            cudaMemcpyAsync(curb, offb, (size_t)8 * (NU + 1) * 4,
                            cudaMemcpyDeviceToDevice, s);
            scatter_all_k<<<dim3((maxE + 255) / 256, 8), 256, 0, s>>>(ep, cfg, curb, srcsb);
        }

        if (l == 0)
            agg_cat_k<<<Nc, 256, 0, s>>>(mkAgg(4), mkAgg(6), bias, 4, 6, l, xc);
        agg_multi_k<<<(Na + 15) / 16, 256, 0, s>>>(
            mkAgg(0), mkAgg(5), mkAgg(0), mkAgg(0), 2,
            bias, make_int4(0, 5, 0, 0), l,
            l == 0 ? xa : nullptr, acc_a, l == 0 ? x_article : nullptr, Na);
        agg_multi_k<<<(Nu + 15) / 16, 256, 0, s>>>(
            mkAgg(1), mkAgg(2), mkAgg(3), mkAgg(7), 4,
            bias, make_int4(1, 2, 3, 7), l,
            l == 0 ? xu : nullptr, acc_u, l == 0 ? x_user : nullptr, Nu);
    }
}